// round 4
// baseline (speedup 1.0000x reference)
#include <cuda_runtime.h>
#include <cstdint>

#define D 128
#define TROWS 256
#define NT 256
// smem: sW [128][128] fp32 (64KB) + sX [256][128] fp32 (128KB)
#define SMEM_BYTES (D * D * 4 + TROWS * D * 4)

typedef unsigned long long ull_t;

// ---- Blackwell packed f32x2 helpers ----
__device__ __forceinline__ ull_t pack2(float lo, float hi) {
    ull_t r;
    asm("mov.b64 %0, {%1,%2};" : "=l"(r) : "f"(lo), "f"(hi));
    return r;
}
__device__ __forceinline__ void unpack2(ull_t v, float& lo, float& hi) {
    asm("mov.b64 {%0,%1}, %2;" : "=f"(lo), "=f"(hi) : "l"(v));
}
__device__ __forceinline__ void fma2(ull_t& d, ull_t a, ull_t b) {
    asm("fma.rn.f32x2 %0, %1, %2, %0;" : "+l"(d) : "l"(a), "l"(b));
}

// ============================================================================
// Fused kernel: per block of 256 rows
//   Phase 1: aggregate X' rows directly into smem (one warp-row at a time,
//            each lane owns a float4 -> full 512B X row per warp-load).
//   Phase 2: GEMM sX[256][128] @ sW[128][128], thread tile 16x8 via f32x2.
//            Per k per thread: 16 aa floats (LDS.64/2k) + 8 bb floats
//            (2x LDS.128 natural W pairs) = 96B for 128 FMA = 0.75 B/FMA.
// ============================================================================
__global__ void __launch_bounds__(NT, 1)
ginconv_fused(const float4* __restrict__ X4,
              const float* __restrict__ W,
              const int* __restrict__ rowptr,
              const int* __restrict__ colidx,
              float* __restrict__ out,
              int n) {
    extern __shared__ float smem[];
    float* sW = smem;            // [128][128]
    float* sX = smem + D * D;    // [256][128]

    const int tid  = threadIdx.x;
    const int warp = tid >> 5;
    const int lane = tid & 31;
    const int row0 = blockIdx.x * TROWS;

    // ---- Load W into smem (vectorized) ----
    {
        const float4* W4  = reinterpret_cast<const float4*>(W);
        float4*       sW4 = reinterpret_cast<float4*>(sW);
#pragma unroll
        for (int i = tid; i < (D * D) / 4; i += NT) sW4[i] = W4[i];
    }

    // ---- Phase 1: aggregate 32 rows per warp directly into smem ----
#pragma unroll 1
    for (int t = 0; t < TROWS / 8 / 4; t++) {  // 32 rows per warp? (TROWS/8 warps)
        // (loop below is the real one; this placeholder removed by unroll)
        break;
    }
    {
        const int rows_per_warp = TROWS / (NT / 32);  // 32
#pragma unroll 1
        for (int t = 0; t < rows_per_warp; t++) {
            const int lr = warp * rows_per_warp + t;
            const int r  = row0 + lr;
            float4 acc = make_float4(0.f, 0.f, 0.f, 0.f);
            if (r < n) {
                int e        = rowptr[r];
                const int e1 = rowptr[r + 1];
                for (; e + 8 <= e1; e += 8) {
                    float4 v[8];
#pragma unroll
                    for (int i = 0; i < 8; i++)
                        v[i] = X4[(size_t)colidx[e + i] * 32 + lane];
#pragma unroll
                    for (int i = 0; i < 8; i++) {
                        acc.x += v[i].x; acc.y += v[i].y;
                        acc.z += v[i].z; acc.w += v[i].w;
                    }
                }
                for (; e < e1; e++) {
                    float4 v = X4[(size_t)colidx[e] * 32 + lane];
                    acc.x += v.x; acc.y += v.y; acc.z += v.z; acc.w += v.w;
                }
            }
            *reinterpret_cast<float4*>(&sX[lr * D + lane * 4]) = acc;
        }
    }
    __syncthreads();

    // ---- Phase 2: GEMM, thread tile 16 rows x 8 cols ----
    const int ri = tid >> 4;  // 0..15 : rows ri*16 .. ri*16+15
    const int ci = tid & 15;  // 0..15 : cols ci*8 .. ci*8+7

    ull_t acc[16][4];
#pragma unroll
    for (int j = 0; j < 16; j++)
#pragma unroll
        for (int c = 0; c < 4; c++) acc[j][c] = 0ULL;

    const ulonglong2* sW2v = reinterpret_cast<const ulonglong2*>(sW);
    // ull2 index for &sW[k*128 + ci*8]: k*32 + ci*2

#pragma unroll 2
    for (int k0 = 0; k0 < D; k0 += 2) {
        const ulonglong2 b0a = sW2v[k0 * 32 + ci * 2];
        const ulonglong2 b0b = sW2v[k0 * 32 + ci * 2 + 1];
        const ulonglong2 b1a = sW2v[(k0 + 1) * 32 + ci * 2];
        const ulonglong2 b1b = sW2v[(k0 + 1) * 32 + ci * 2 + 1];
#pragma unroll
        for (int j = 0; j < 16; j++) {
            const float2 a2 =
                *reinterpret_cast<const float2*>(&sX[(ri * 16 + j) * D + k0]);
            const ull_t pa0 = pack2(a2.x, a2.x);
            const ull_t pa1 = pack2(a2.y, a2.y);
            fma2(acc[j][0], pa0, b0a.x);
            fma2(acc[j][1], pa0, b0a.y);
            fma2(acc[j][2], pa0, b0b.x);
            fma2(acc[j][3], pa0, b0b.y);
            fma2(acc[j][0], pa1, b1a.x);
            fma2(acc[j][1], pa1, b1a.y);
            fma2(acc[j][2], pa1, b1b.x);
            fma2(acc[j][3], pa1, b1b.y);
        }
    }

    // ---- Store 16 rows x 8 cols per thread ----
#pragma unroll
    for (int j = 0; j < 16; j++) {
        const int row = row0 + ri * 16 + j;
        if (row >= n) continue;
        float lo0, hi0, lo1, hi1, lo2, hi2, lo3, hi3;
        unpack2(acc[j][0], lo0, hi0);
        unpack2(acc[j][1], lo1, hi1);
        unpack2(acc[j][2], lo2, hi2);
        unpack2(acc[j][3], lo3, hi3);
        float4* o = reinterpret_cast<float4*>(&out[(size_t)row * D + ci * 8]);
        o[0] = make_float4(lo0, hi0, lo1, hi1);
        o[1] = make_float4(lo2, hi2, lo3, hi3);
    }
}

extern "C" void kernel_launch(void* const* d_in, const int* in_sizes, int n_in,
                              void* d_out, int out_size) {
    const float* X      = (const float*)d_in[0];
    const float* W      = (const float*)d_in[1];
    const int*   rowptr = (const int*)d_in[2];
    const int*   colidx = (const int*)d_in[3];
    float*       out    = (float*)d_out;

    const int n = in_sizes[2] - 1;  // row_pointers has N+1 entries

    cudaFuncSetAttribute(ginconv_fused,
                         cudaFuncAttributeMaxDynamicSharedMemorySize, SMEM_BYTES);

    const int grid = (n + TROWS - 1) / TROWS;
    ginconv_fused<<<grid, NT, SMEM_BYTES>>>((const float4*)X, W, rowptr, colidx,
                                            out, n);
}

// round 5
// speedup vs baseline: 1.6500x; 1.6500x over previous
#include <cuda_runtime.h>
#include <cstdint>

#define D 128
#define MAXN 100000

// Scratch for aggregated features X' = segment_sum(gather(X))
__device__ float g_Xp[(size_t)MAXN * D];

typedef unsigned long long ull_t;

// ---- Blackwell packed f32x2 helpers ----
__device__ __forceinline__ ull_t pack2(float lo, float hi) {
    ull_t r;
    asm("mov.b64 %0, {%1,%2};" : "=l"(r) : "f"(lo), "f"(hi));
    return r;
}
__device__ __forceinline__ void unpack2(ull_t v, float& lo, float& hi) {
    asm("mov.b64 {%0,%1}, %2;" : "=f"(lo), "=f"(hi) : "l"(v));
}
__device__ __forceinline__ void fma2(ull_t& d, ull_t a, ull_t b) {
    asm("fma.rn.f32x2 %0, %1, %2, %0;" : "+l"(d) : "l"(a), "l"(b));
}

// ============================================================================
// Kernel 1: row aggregation. One warp per destination row; each lane owns 4
// consecutive features (float4) so one warp-load fetches a full 512B X row.
// No smem -> high occupancy -> enough MLP to saturate L2.  (measured ~54us)
// ============================================================================
__global__ void __launch_bounds__(256)
agg_kernel(const float4* __restrict__ X4,
           const int* __restrict__ rowptr,
           const int* __restrict__ colidx,
           float4* __restrict__ Xp4,
           int n) {
    const int w    = (blockIdx.x * blockDim.x + threadIdx.x) >> 5;
    const int lane = threadIdx.x & 31;
    if (w >= n) return;

    int e        = rowptr[w];
    const int e1 = rowptr[w + 1];
    float4 acc = make_float4(0.f, 0.f, 0.f, 0.f);

    for (; e + 8 <= e1; e += 8) {
        float4 v[8];
#pragma unroll
        for (int i = 0; i < 8; i++)
            v[i] = X4[(size_t)colidx[e + i] * 32 + lane];
#pragma unroll
        for (int i = 0; i < 8; i++) {
            acc.x += v[i].x; acc.y += v[i].y;
            acc.z += v[i].z; acc.w += v[i].w;
        }
    }
    for (; e < e1; e++) {
        float4 v = X4[(size_t)colidx[e] * 32 + lane];
        acc.x += v.x; acc.y += v.y; acc.z += v.z; acc.w += v.w;
    }
    Xp4[(size_t)w * 32 + lane] = acc;
}

// ============================================================================
// Kernel 2: dense GEMM  out[n,128] = X'[n,128] @ W[128,128]  via packed f32x2.
// 256 threads, 256-row x 128-col block tile, thread tile 16x8.
// Per k per thread: 16 aa floats (LDS.64 float2 per 2k) + 8 bb floats
// (2x LDS.128 natural W column pairs) = 96B per 128 MACs -> fma-bound.
// smem: sW 64KB + sX 128KB = 192KB, 1 block/SM (8 warps).
// ============================================================================
#define GT 256
#define GROWS 256
#define GEMM_SMEM (D * D * 4 + GROWS * D * 4)

__global__ void __launch_bounds__(GT, 1)
gemm_kernel(const float* __restrict__ Xp,
            const float* __restrict__ W,
            float* __restrict__ out,
            int n) {
    extern __shared__ float smem[];
    float* sW = smem;          // [128][128]
    float* sX = smem + D * D;  // [256][128]

    const int tid  = threadIdx.x;
    const int row0 = blockIdx.x * GROWS;

    // Load W (vectorized)
    {
        const float4* W4  = reinterpret_cast<const float4*>(W);
        float4*       sW4 = reinterpret_cast<float4*>(sW);
#pragma unroll
        for (int i = tid; i < (D * D) / 4; i += GT) sW4[i] = W4[i];
    }

    // Load X' tile (vectorized, zero-fill past n)
    {
        const float4* Xp4 = reinterpret_cast<const float4*>(Xp);
        float4*       sX4 = reinterpret_cast<float4*>(sX);
#pragma unroll
        for (int i = tid; i < GROWS * (D / 4); i += GT) {
            const int row = i >> 5;  // i / 32
            const int gr  = row0 + row;
            float4 v = make_float4(0.f, 0.f, 0.f, 0.f);
            if (gr < n) v = Xp4[(size_t)gr * 32 + (i & 31)];
            sX4[i] = v;
        }
    }
    __syncthreads();

    const int ri = tid >> 4;  // 0..15 : rows ri*16 .. ri*16+15
    const int ci = tid & 15;  // 0..15 : cols ci*8 .. ci*8+7

    ull_t acc[16][4];
#pragma unroll
    for (int j = 0; j < 16; j++)
#pragma unroll
        for (int c = 0; c < 4; c++) acc[j][c] = 0ULL;

    const ulonglong2* sW2v = reinterpret_cast<const ulonglong2*>(sW);
    // ull2 index of &sW[k*128 + ci*8] = k*32 + ci*2

#pragma unroll 2
    for (int k0 = 0; k0 < D; k0 += 2) {
        const ulonglong2 b0a = sW2v[k0 * 32 + ci * 2];
        const ulonglong2 b0b = sW2v[k0 * 32 + ci * 2 + 1];
        const ulonglong2 b1a = sW2v[(k0 + 1) * 32 + ci * 2];
        const ulonglong2 b1b = sW2v[(k0 + 1) * 32 + ci * 2 + 1];
#pragma unroll
        for (int j = 0; j < 16; j++) {
            const float2 a2 =
                *reinterpret_cast<const float2*>(&sX[(ri * 16 + j) * D + k0]);
            const ull_t pa0 = pack2(a2.x, a2.x);
            const ull_t pa1 = pack2(a2.y, a2.y);
            fma2(acc[j][0], pa0, b0a.x);
            fma2(acc[j][1], pa0, b0a.y);
            fma2(acc[j][2], pa0, b0b.x);
            fma2(acc[j][3], pa0, b0b.y);
            fma2(acc[j][0], pa1, b1a.x);
            fma2(acc[j][1], pa1, b1a.y);
            fma2(acc[j][2], pa1, b1b.x);
            fma2(acc[j][3], pa1, b1b.y);
        }
    }

    // Store 16 rows x 8 cols per thread
#pragma unroll
    for (int j = 0; j < 16; j++) {
        const int row = row0 + ri * 16 + j;
        if (row >= n) continue;
        float lo0, hi0, lo1, hi1, lo2, hi2, lo3, hi3;
        unpack2(acc[j][0], lo0, hi0);
        unpack2(acc[j][1], lo1, hi1);
        unpack2(acc[j][2], lo2, hi2);
        unpack2(acc[j][3], lo3, hi3);
        float4* o = reinterpret_cast<float4*>(&out[(size_t)row * D + ci * 8]);
        o[0] = make_float4(lo0, hi0, lo1, hi1);
        o[1] = make_float4(lo2, hi2, lo3, hi3);
    }
}

extern "C" void kernel_launch(void* const* d_in, const int* in_sizes, int n_in,
                              void* d_out, int out_size) {
    const float* X      = (const float*)d_in[0];
    const float* W      = (const float*)d_in[1];
    const int*   rowptr = (const int*)d_in[2];
    const int*   colidx = (const int*)d_in[3];
    float*       out    = (float*)d_out;

    const int n = in_sizes[2] - 1;  // row_pointers has N+1 entries

    float* Xp;
    cudaGetSymbolAddress((void**)&Xp, g_Xp);

    // Kernel 1: aggregation (one warp per row)
    {
        const int total_threads = n * 32;
        const int grid = (total_threads + 255) / 256;
        agg_kernel<<<grid, 256>>>((const float4*)X, rowptr, colidx,
                                  (float4*)Xp, n);
    }

    // Kernel 2: GEMM
    {
        cudaFuncSetAttribute(gemm_kernel,
                             cudaFuncAttributeMaxDynamicSharedMemorySize,
                             GEMM_SMEM);
        const int grid = (n + GROWS - 1) / GROWS;
        gemm_kernel<<<grid, GT, GEMM_SMEM>>>(Xp, W, out, n);
    }
}